// round 4
// baseline (speedup 1.0000x reference)
#include <cuda_runtime.h>
#include <cstdint>

#define BB 8
#define NN 4096
#define HALF 2048
#define KK 16
#define THREADS 256
#define QPB 128          // queries per block
#define SLOTSH 40        // collect slots per half
#define FLTMAX 3.402823466e38f

// smem: xs,ys,zs,ss (4*4096*4 = 64KB) + si u16[2*SLOTSH][128] (20KB) + scnt (1KB)
#define SMEM_BYTES ((4 * NN) * 4 + (2 * SLOTSH * QPB) * 2 + THREADS * 4)

// ---------------- packed f32x2 helpers ----------------
__device__ __forceinline__ unsigned long long pk2(float v) {
    unsigned long long r;
    asm("mov.b64 %0, {%1, %1};" : "=l"(r) : "f"(v));
    return r;
}
__device__ __forceinline__ unsigned long long mul2_(unsigned long long a, unsigned long long b) {
    unsigned long long r;
    asm("mul.rn.f32x2 %0, %1, %2;" : "=l"(r) : "l"(a), "l"(b));
    return r;
}
__device__ __forceinline__ unsigned long long add2_(unsigned long long a, unsigned long long b) {
    unsigned long long r;
    asm("add.rn.f32x2 %0, %1, %2;" : "=l"(r) : "l"(a), "l"(b));
    return r;
}
__device__ __forceinline__ unsigned long long fma2_(unsigned long long a, unsigned long long b,
                                                    unsigned long long c) {
    unsigned long long r;
    asm("fma.rn.f32x2 %0, %1, %2, %3;" : "=l"(r) : "l"(a), "l"(b), "l"(c));
    return r;
}
__device__ __forceinline__ void unpk2(unsigned long long v, float& lo, float& hi) {
    asm("mov.b64 {%0, %1}, %2;" : "=f"(lo), "=f"(hi) : "l"(v));
}

// Distance for 2 candidates with precomputed candidate norm s2 (bitwise == scalar path):
//   in = fmaf(z,zq, fmaf(y,yq, x*xq));  d = fmaf(-2, in, sq + sm)
__device__ __forceinline__ unsigned long long dist2p(
    unsigned long long x2, unsigned long long y2, unsigned long long z2, unsigned long long s2,
    unsigned long long xq2, unsigned long long yq2, unsigned long long zq2,
    unsigned long long sq2, unsigned long long n2) {
    unsigned long long in = fma2_(z2, zq2, fma2_(y2, yq2, mul2_(x2, xq2)));
    return fma2_(n2, in, add2_(sq2, s2));
}

// Scalar distance, bitwise-identical to dist2p lanes.
__device__ __forceinline__ float dists(float x, float y, float z, float sm,
                                       float xq, float yq, float zq, float sq) {
    float in = fmaf(z, zq, fmaf(y, yq, x * xq));
    return fmaf(-2.0f, in, sq + sm);
}

// Values-only sorted-16 insert (branch-free min/max shift)
__device__ __forceinline__ void insert16(float v[16], float d) {
#pragma unroll
    for (int j = 15; j >= 1; --j)
        v[j] = fminf(v[j], fmaxf(v[j - 1], d));
    v[0] = fminf(v[0], d);
}

// (d, idx) lexicographic pair-insert into sorted 16-list (lax.top_k order)
__device__ __forceinline__ void pins(float rd[16], int ri[16], float d, int i) {
    bool lessLast = (d < rd[15]) || (d == rd[15] && i < ri[15]);
    if (!lessLast) return;
#pragma unroll
    for (int j = 15; j >= 1; --j) {
        bool le = (d < rd[j - 1]) || (d == rd[j - 1] && i < ri[j - 1]);
        bool lj = (d < rd[j]) || (d == rd[j] && i < ri[j]);
        rd[j] = le ? rd[j - 1] : (lj ? d : rd[j]);
        ri[j] = le ? ri[j - 1] : (lj ? i : ri[j]);
    }
    bool l0 = (d < rd[0]) || (d == rd[0] && i < ri[0]);
    if (l0) { rd[0] = d; ri[0] = i; }
}

extern __shared__ char smem_raw[];

__global__ void __launch_bounds__(THREADS, 2)
knn_edge_kernel(const float* __restrict__ cloud, float* __restrict__ out) {
    float* xs = (float*)smem_raw;
    float* ys = xs + NN;
    float* zs = ys + NN;
    float* ss = zs + NN;
    unsigned short* si = (unsigned short*)(ss + NN);   // [2*SLOTSH][QPB]
    int* scnt = (int*)(si + 2 * SLOTSH * QPB);         // [THREADS]

    const int tid = threadIdx.x;
    const int qc  = tid & (QPB - 1);
    const int h   = tid >> 7;          // half 0/1
    const int b    = blockIdx.x >> 5;
    const int tile = blockIdx.x & 31;
    const int q    = tile * QPB + qc;

    // ---- Load batch cloud to SMEM (SoA) + precompute norms ----
    const float4* cb4 = (const float4*)(cloud + (size_t)b * 3 * NN);
    float4* xs4 = (float4*)xs; float4* ys4 = (float4*)ys;
    float4* zs4 = (float4*)zs; float4* ss4 = (float4*)ss;
    for (int i = tid; i < NN / 4; i += THREADS) {
        xs4[i] = cb4[i];
        ys4[i] = cb4[NN / 4 + i];
        zs4[i] = cb4[2 * (NN / 4) + i];
    }
    __syncthreads();
    for (int i = tid; i < NN / 4; i += THREADS) {
        float4 X = xs4[i], Y = ys4[i], Z = zs4[i], S;
        S.x = fmaf(X.x, X.x, fmaf(Y.x, Y.x, Z.x * Z.x));
        S.y = fmaf(X.y, X.y, fmaf(Y.y, Y.y, Z.y * Z.y));
        S.z = fmaf(X.z, X.z, fmaf(Y.z, Y.z, Z.z * Z.z));
        S.w = fmaf(X.w, X.w, fmaf(Y.w, Y.w, Z.w * Z.w));
        ss4[i] = S;
    }
    __syncthreads();

    const float xq = xs[q], yq = ys[q], zq = zs[q], sq = ss[q];
    const unsigned long long xq2 = pk2(xq), yq2 = pk2(yq), zq2 = pk2(zq);
    const unsigned long long sq2 = pk2(sq), n2 = pk2(-2.0f);

    const ulonglong2* xs2 = (const ulonglong2*)xs;
    const ulonglong2* ys2 = (const ulonglong2*)ys;
    const ulonglong2* zs2 = (const ulonglong2*)zs;
    const ulonglong2* ss2 = (const ulonglong2*)ss;

    const int mstart = h * HALF;

    // ---- Pass 1: depth-1 32-bucket min sketch (1 FMNMX per candidate) ----
    float m[32];
#pragma unroll
    for (int t = 0; t < 32; ++t) m[t] = FLTMAX;

#pragma unroll 1
    for (int it = 0; it < HALF / 32; ++it) {
        const int p0 = (mstart >> 2) + it * 8;
#pragma unroll
        for (int j = 0; j < 8; ++j) {
            ulonglong2 X = xs2[p0 + j], Y = ys2[p0 + j], Z = zs2[p0 + j], S = ss2[p0 + j];
            float d0, d1, d2v, d3;
            unpk2(dist2p(X.x, Y.x, Z.x, S.x, xq2, yq2, zq2, sq2, n2), d0, d1);
            unpk2(dist2p(X.y, Y.y, Z.y, S.y, xq2, yq2, zq2, sq2, n2), d2v, d3);
            m[4 * j + 0] = fminf(m[4 * j + 0], d0);
            m[4 * j + 1] = fminf(m[4 * j + 1], d1);
            m[4 * j + 2] = fminf(m[4 * j + 2], d2v);
            m[4 * j + 3] = fminf(m[4 * j + 3], d3);
        }
    }

    // T = 16th smallest of the 32 bucket minima  (subset order stat => T >= exact d16)
    float v[16];
#pragma unroll
    for (int t = 0; t < 16; ++t) v[t] = FLTMAX;
#pragma unroll
    for (int t = 0; t < 32; ++t) insert16(v, m[t]);
    const float T = v[15];

    // ---- Pass 2: collect indices of all d <= T (bitwise-identical recompute) ----
    const int rowbase = h * SLOTSH;
    int cnt = 0;
#pragma unroll 1
    for (int it = 0; it < HALF / 16; ++it) {
        const int c0 = mstart + it * 16;
        const int p0 = c0 >> 2;
        float dd[16];
#pragma unroll
        for (int j = 0; j < 4; ++j) {
            ulonglong2 X = xs2[p0 + j], Y = ys2[p0 + j], Z = zs2[p0 + j], S = ss2[p0 + j];
            unpk2(dist2p(X.x, Y.x, Z.x, S.x, xq2, yq2, zq2, sq2, n2), dd[4 * j + 0], dd[4 * j + 1]);
            unpk2(dist2p(X.y, Y.y, Z.y, S.y, xq2, yq2, zq2, sq2, n2), dd[4 * j + 2], dd[4 * j + 3]);
        }
#pragma unroll
        for (int g = 0; g < 2; ++g) {
            float mn = fminf(fminf(fminf(dd[8 * g + 0], dd[8 * g + 1]), fminf(dd[8 * g + 2], dd[8 * g + 3])),
                             fminf(fminf(dd[8 * g + 4], dd[8 * g + 5]), fminf(dd[8 * g + 6], dd[8 * g + 7])));
            if (mn <= T) {
#pragma unroll
                for (int k = 0; k < 8; ++k) {
                    bool pr = (dd[8 * g + k] <= T) && (cnt < SLOTSH);
                    if (pr) si[(rowbase + cnt) * QPB + qc] = (unsigned short)(c0 + 8 * g + k);
                    cnt += pr;
                }
            }
        }
    }

    // ---- Overflow fallback (rare): exact pair top-16 rescan of this half ----
    if (cnt >= SLOTSH) {
        float rdF[16]; int riF[16];
#pragma unroll
        for (int t = 0; t < 16; ++t) { rdF[t] = FLTMAX; riF[t] = 0; }
        for (int mm = mstart; mm < mstart + HALF; ++mm) {
            float d = dists(xs[mm], ys[mm], zs[mm], ss[mm], xq, yq, zq, sq);
            pins(rdF, riF, d, mm);
        }
#pragma unroll
        for (int t = 0; t < 16; ++t)
            si[(rowbase + t) * QPB + qc] = (unsigned short)riF[t];
        cnt = 16;
    }
    scnt[tid] = cnt;
    __syncthreads();

    // ---- Exact selection over both halves' survivors (threads 0..127) ----
    float rd[16]; int ri[16];
    if (tid < QPB) {
#pragma unroll
        for (int t = 0; t < 16; ++t) { rd[t] = FLTMAX; ri[t] = 0; }
        const int c1 = scnt[tid];
        for (int s = 0; s < c1; ++s) {
            int ii = (int)si[s * QPB + tid];
            float d = dists(xs[ii], ys[ii], zs[ii], ss[ii], xq, yq, zq, sq);
            pins(rd, ri, d, ii);
        }
        const int c2 = scnt[QPB + tid];
        for (int s = 0; s < c2; ++s) {
            int ii = (int)si[(SLOTSH + s) * QPB + tid];
            float d = dists(xs[ii], ys[ii], zs[ii], ss[ii], xq, yq, zq, sq);
            pins(rd, ri, d, ii);
        }
        // hand off sorted indices to the upper-half partner thread
#pragma unroll
        for (int t = 0; t < 16; ++t)
            si[t * QPB + tid] = (unsigned short)ri[t];
    }
    __syncthreads();

    // ---- Emit edge features: out[b][c][q][k]; channels split across halves ----
    const size_t base = (((size_t)b * 6) * NN + q) * KK;
    if (tid < QPB) {
        float cvals[3] = {xq, yq, zq};
#pragma unroll
        for (int c = 0; c < 3; ++c) {
            float4 vv = make_float4(cvals[c], cvals[c], cvals[c], cvals[c]);
            float4* op = (float4*)(out + base + (size_t)c * NN * KK);
            op[0] = vv; op[1] = vv; op[2] = vv; op[3] = vv;
        }
        float nx[16];
#pragma unroll
        for (int k = 0; k < 16; ++k) nx[k] = xs[ri[k]] - xq;
        float4* op = (float4*)(out + base + (size_t)3 * NN * KK);
        op[0] = make_float4(nx[0], nx[1], nx[2], nx[3]);
        op[1] = make_float4(nx[4], nx[5], nx[6], nx[7]);
        op[2] = make_float4(nx[8], nx[9], nx[10], nx[11]);
        op[3] = make_float4(nx[12], nx[13], nx[14], nx[15]);
    } else {
        int rr[16];
#pragma unroll
        for (int k = 0; k < 16; ++k) rr[k] = (int)si[k * QPB + qc];
        float ny[16], nz[16];
#pragma unroll
        for (int k = 0; k < 16; ++k) {
            ny[k] = ys[rr[k]] - yq;
            nz[k] = zs[rr[k]] - zq;
        }
        float4* op = (float4*)(out + base + (size_t)4 * NN * KK);
        op[0] = make_float4(ny[0], ny[1], ny[2], ny[3]);
        op[1] = make_float4(ny[4], ny[5], ny[6], ny[7]);
        op[2] = make_float4(ny[8], ny[9], ny[10], ny[11]);
        op[3] = make_float4(ny[12], ny[13], ny[14], ny[15]);
        op = (float4*)(out + base + (size_t)5 * NN * KK);
        op[0] = make_float4(nz[0], nz[1], nz[2], nz[3]);
        op[1] = make_float4(nz[4], nz[5], nz[6], nz[7]);
        op[2] = make_float4(nz[8], nz[9], nz[10], nz[11]);
        op[3] = make_float4(nz[12], nz[13], nz[14], nz[15]);
    }
}

extern "C" void kernel_launch(void* const* d_in, const int* in_sizes, int n_in,
                              void* d_out, int out_size) {
    const float* cloud = (const float*)d_in[0];
    float* out = (float*)d_out;

    cudaFuncSetAttribute(knn_edge_kernel,
                         cudaFuncAttributeMaxDynamicSharedMemorySize, SMEM_BYTES);

    dim3 grid(BB * (NN / QPB));   // 256 blocks
    dim3 block(THREADS);
    knn_edge_kernel<<<grid, block, SMEM_BYTES>>>(cloud, out);
}

// round 5
// speedup vs baseline: 1.8178x; 1.8178x over previous
#include <cuda_runtime.h>
#include <cstdint>

#define BB 8
#define NN 4096
#define HALF 2048
#define KK 16
#define THREADS 256
#define QPB 128          // queries per block
#define SLOTSH 32        // collect slots per half
#define FLTMAX 3.402823466e38f

// smem: xs,ys,zs,ss (4*4096*4 = 64KB) + si u16[2*SLOTSH][128] (16KB) + scnt (1KB)
#define SMEM_BYTES ((4 * NN) * 4 + (2 * SLOTSH * QPB) * 2 + THREADS * 4)

// ---------------- packed f32x2 helpers ----------------
__device__ __forceinline__ unsigned long long pk2(float v) {
    unsigned long long r;
    asm("mov.b64 %0, {%1, %1};" : "=l"(r) : "f"(v));
    return r;
}
__device__ __forceinline__ unsigned long long mul2_(unsigned long long a, unsigned long long b) {
    unsigned long long r;
    asm("mul.rn.f32x2 %0, %1, %2;" : "=l"(r) : "l"(a), "l"(b));
    return r;
}
__device__ __forceinline__ unsigned long long add2_(unsigned long long a, unsigned long long b) {
    unsigned long long r;
    asm("add.rn.f32x2 %0, %1, %2;" : "=l"(r) : "l"(a), "l"(b));
    return r;
}
__device__ __forceinline__ unsigned long long fma2_(unsigned long long a, unsigned long long b,
                                                    unsigned long long c) {
    unsigned long long r;
    asm("fma.rn.f32x2 %0, %1, %2, %3;" : "=l"(r) : "l"(a), "l"(b), "l"(c));
    return r;
}
__device__ __forceinline__ void unpk2(unsigned long long v, float& lo, float& hi) {
    asm("mov.b64 {%0, %1}, %2;" : "=f"(lo), "=f"(hi) : "l"(v));
}

// Packed distance with precomputed candidate norm s2. Per-lane ops:
//   in = fmaf(z,zq, fmaf(y,yq, x*xq));  d = fmaf(-2, in, sq + s)
__device__ __forceinline__ unsigned long long dist2p(
    unsigned long long x2, unsigned long long y2, unsigned long long z2, unsigned long long s2,
    unsigned long long xq2, unsigned long long yq2, unsigned long long zq2,
    unsigned long long sq2, unsigned long long n2) {
    unsigned long long in = fma2_(z2, zq2, fma2_(y2, yq2, mul2_(x2, xq2)));
    return fma2_(n2, in, add2_(sq2, s2));
}

// Scalar distance, bitwise-identical to dist2p lanes (.rn IEEE both paths).
__device__ __forceinline__ float dists(float x, float y, float z, float sm,
                                       float xq, float yq, float zq, float sq) {
    float in = fmaf(z, zq, fmaf(y, yq, x * xq));
    return fmaf(-2.0f, in, sq + sm);
}

// Values-only sorted-16 insert (branch-free min/max shift)
__device__ __forceinline__ void insert16(float v[16], float d) {
#pragma unroll
    for (int j = 15; j >= 1; --j)
        v[j] = fminf(v[j], fmaxf(v[j - 1], d));
    v[0] = fminf(v[0], d);
}

// (d, idx) lexicographic pair-insert into sorted 16-list (lax.top_k order)
__device__ __forceinline__ void pins(float rd[16], int ri[16], float d, int i) {
    bool lessLast = (d < rd[15]) || (d == rd[15] && i < ri[15]);
    if (!lessLast) return;
#pragma unroll
    for (int j = 15; j >= 1; --j) {
        bool le = (d < rd[j - 1]) || (d == rd[j - 1] && i < ri[j - 1]);
        bool lj = (d < rd[j]) || (d == rd[j] && i < ri[j]);
        rd[j] = le ? rd[j - 1] : (lj ? d : rd[j]);
        ri[j] = le ? ri[j - 1] : (lj ? i : ri[j]);
    }
    bool l0 = (d < rd[0]) || (d == rd[0] && i < ri[0]);
    if (l0) { rd[0] = d; ri[0] = i; }
}

extern __shared__ char smem_raw[];

__global__ void __launch_bounds__(THREADS, 2)
knn_edge_kernel(const float* __restrict__ cloud, float* __restrict__ out) {
    float* xs = (float*)smem_raw;
    float* ys = xs + NN;
    float* zs = ys + NN;
    float* ss = zs + NN;
    unsigned short* si = (unsigned short*)(ss + NN);   // [2*SLOTSH][QPB]
    int* scnt = (int*)(si + 2 * SLOTSH * QPB);         // [THREADS]

    const int tid = threadIdx.x;
    const int qc  = tid & (QPB - 1);
    const int h   = tid >> 7;          // half 0/1
    const int b    = blockIdx.x >> 5;
    const int tile = blockIdx.x & 31;
    const int q    = tile * QPB + qc;

    // ---- Load batch cloud to SMEM (SoA) + precompute norms ----
    const float4* cb4 = (const float4*)(cloud + (size_t)b * 3 * NN);
    float4* xs4 = (float4*)xs; float4* ys4 = (float4*)ys;
    float4* zs4 = (float4*)zs; float4* ss4 = (float4*)ss;
    for (int i = tid; i < NN / 4; i += THREADS) {
        xs4[i] = cb4[i];
        ys4[i] = cb4[NN / 4 + i];
        zs4[i] = cb4[2 * (NN / 4) + i];
    }
    __syncthreads();
    for (int i = tid; i < NN / 4; i += THREADS) {
        float4 X = xs4[i], Y = ys4[i], Z = zs4[i], S;
        S.x = fmaf(X.x, X.x, fmaf(Y.x, Y.x, Z.x * Z.x));
        S.y = fmaf(X.y, X.y, fmaf(Y.y, Y.y, Z.y * Z.y));
        S.z = fmaf(X.z, X.z, fmaf(Y.z, Y.z, Z.z * Z.z));
        S.w = fmaf(X.w, X.w, fmaf(Y.w, Y.w, Z.w * Z.w));
        ss4[i] = S;
    }
    __syncthreads();

    const float xq = xs[q], yq = ys[q], zq = zs[q], sq = ss[q];
    const unsigned long long xq2 = pk2(xq), yq2 = pk2(yq), zq2 = pk2(zq);
    const unsigned long long sq2 = pk2(sq), n2 = pk2(-2.0f);

    const ulonglong2* xs2 = (const ulonglong2*)xs;
    const ulonglong2* ys2 = (const ulonglong2*)ys;
    const ulonglong2* zs2 = (const ulonglong2*)zs;
    const ulonglong2* ss2 = (const ulonglong2*)ss;

    const int mstart = h * HALF;

    // ---- Pass 1: branch-free 16-bucket depth-2 min sketch over this half ----
    float m1[16], m2[16];
#pragma unroll
    for (int t = 0; t < 16; ++t) { m1[t] = FLTMAX; m2[t] = FLTMAX; }

#pragma unroll 1
    for (int it = 0; it < HALF / 16; ++it) {
        const int p0 = (mstart >> 2) + it * 4;
#pragma unroll
        for (int j = 0; j < 4; ++j) {
            ulonglong2 X = xs2[p0 + j], Y = ys2[p0 + j], Z = zs2[p0 + j], S = ss2[p0 + j];
            float d0, d1, d2v, d3;
            unpk2(dist2p(X.x, Y.x, Z.x, S.x, xq2, yq2, zq2, sq2, n2), d0, d1);
            unpk2(dist2p(X.y, Y.y, Z.y, S.y, xq2, yq2, zq2, sq2, n2), d2v, d3);
            const int t0 = j * 4;
            m2[t0 + 0] = fminf(m2[t0 + 0], fmaxf(m1[t0 + 0], d0)); m1[t0 + 0] = fminf(m1[t0 + 0], d0);
            m2[t0 + 1] = fminf(m2[t0 + 1], fmaxf(m1[t0 + 1], d1)); m1[t0 + 1] = fminf(m1[t0 + 1], d1);
            m2[t0 + 2] = fminf(m2[t0 + 2], fmaxf(m1[t0 + 2], d2v)); m1[t0 + 2] = fminf(m1[t0 + 2], d2v);
            m2[t0 + 3] = fminf(m2[t0 + 3], fmaxf(m1[t0 + 3], d3)); m1[t0 + 3] = fminf(m1[t0 + 3], d3);
        }
    }

    // T = 16th smallest of the 32 stored sketch values (>= exact d16 of this half)
    float v[16];
#pragma unroll
    for (int t = 0; t < 16; ++t) v[t] = FLTMAX;
#pragma unroll
    for (int t = 0; t < 16; ++t) { insert16(v, m1[t]); insert16(v, m2[t]); }
    const float T = v[15];

    // ---- Pass 2: collect indices of all d <= T (bitwise-identical recompute) ----
    const int rowbase = h * SLOTSH;
    int cnt = 0;
#pragma unroll 1
    for (int it = 0; it < HALF / 16; ++it) {
        const int c0 = mstart + it * 16;
        const int p0 = c0 >> 2;
#pragma unroll
        for (int j = 0; j < 4; ++j) {
            ulonglong2 X = xs2[p0 + j], Y = ys2[p0 + j], Z = zs2[p0 + j], S = ss2[p0 + j];
            float dd[4];
            unpk2(dist2p(X.x, Y.x, Z.x, S.x, xq2, yq2, zq2, sq2, n2), dd[0], dd[1]);
            unpk2(dist2p(X.y, Y.y, Z.y, S.y, xq2, yq2, zq2, sq2, n2), dd[2], dd[3]);
#pragma unroll
            for (int k = 0; k < 4; ++k) {
                bool pr = (dd[k] <= T) && (cnt < SLOTSH);
                if (pr) si[(rowbase + cnt) * QPB + qc] = (unsigned short)(c0 + j * 4 + k);
                cnt += pr;
            }
        }
    }

    // ---- Overflow fallback (rare): exact pair top-16 rescan of this half ----
    if (cnt >= SLOTSH) {
        float rdF[16]; int riF[16];
#pragma unroll
        for (int t = 0; t < 16; ++t) { rdF[t] = FLTMAX; riF[t] = 0; }
        for (int mm = mstart; mm < mstart + HALF; ++mm) {
            float d = dists(xs[mm], ys[mm], zs[mm], ss[mm], xq, yq, zq, sq);
            pins(rdF, riF, d, mm);
        }
#pragma unroll
        for (int t = 0; t < 16; ++t)
            si[(rowbase + t) * QPB + qc] = (unsigned short)riF[t];
        cnt = 16;
    }
    scnt[tid] = cnt;
    __syncthreads();

    // ---- Exact selection over both halves' survivors (threads 0..127) ----
    float rd[16]; int ri[16];
    if (tid < QPB) {
#pragma unroll
        for (int t = 0; t < 16; ++t) { rd[t] = FLTMAX; ri[t] = 0; }
        const int c1 = scnt[tid];
        for (int s = 0; s < c1; ++s) {
            int ii = (int)si[s * QPB + tid];
            float d = dists(xs[ii], ys[ii], zs[ii], ss[ii], xq, yq, zq, sq);
            pins(rd, ri, d, ii);
        }
        const int c2 = scnt[QPB + tid];
        for (int s = 0; s < c2; ++s) {
            int ii = (int)si[(SLOTSH + s) * QPB + tid];
            float d = dists(xs[ii], ys[ii], zs[ii], ss[ii], xq, yq, zq, sq);
            pins(rd, ri, d, ii);
        }
        // hand off sorted indices to the upper-half partner thread
#pragma unroll
        for (int t = 0; t < 16; ++t)
            si[t * QPB + tid] = (unsigned short)ri[t];
    }
    __syncthreads();

    // ---- Emit edge features: out[b][c][q][k]; channels split across halves ----
    const size_t base = (((size_t)b * 6) * NN + q) * KK;
    if (tid < QPB) {
        float cvals[3] = {xq, yq, zq};
#pragma unroll
        for (int c = 0; c < 3; ++c) {
            float4 vv = make_float4(cvals[c], cvals[c], cvals[c], cvals[c]);
            float4* op = (float4*)(out + base + (size_t)c * NN * KK);
            op[0] = vv; op[1] = vv; op[2] = vv; op[3] = vv;
        }
        float nx[16];
#pragma unroll
        for (int k = 0; k < 16; ++k) nx[k] = xs[ri[k]] - xq;
        float4* op = (float4*)(out + base + (size_t)3 * NN * KK);
        op[0] = make_float4(nx[0], nx[1], nx[2], nx[3]);
        op[1] = make_float4(nx[4], nx[5], nx[6], nx[7]);
        op[2] = make_float4(nx[8], nx[9], nx[10], nx[11]);
        op[3] = make_float4(nx[12], nx[13], nx[14], nx[15]);
    } else {
        int rr[16];
#pragma unroll
        for (int k = 0; k < 16; ++k) rr[k] = (int)si[k * QPB + qc];
        float ny[16], nz[16];
#pragma unroll
        for (int k = 0; k < 16; ++k) {
            ny[k] = ys[rr[k]] - yq;
            nz[k] = zs[rr[k]] - zq;
        }
        float4* op = (float4*)(out + base + (size_t)4 * NN * KK);
        op[0] = make_float4(ny[0], ny[1], ny[2], ny[3]);
        op[1] = make_float4(ny[4], ny[5], ny[6], ny[7]);
        op[2] = make_float4(ny[8], ny[9], ny[10], ny[11]);
        op[3] = make_float4(ny[12], ny[13], ny[14], ny[15]);
        op = (float4*)(out + base + (size_t)5 * NN * KK);
        op[0] = make_float4(nz[0], nz[1], nz[2], nz[3]);
        op[1] = make_float4(nz[4], nz[5], nz[6], nz[7]);
        op[2] = make_float4(nz[8], nz[9], nz[10], nz[11]);
        op[3] = make_float4(nz[12], nz[13], nz[14], nz[15]);
    }
}

extern "C" void kernel_launch(void* const* d_in, const int* in_sizes, int n_in,
                              void* d_out, int out_size) {
    const float* cloud = (const float*)d_in[0];
    float* out = (float*)d_out;

    cudaFuncSetAttribute(knn_edge_kernel,
                         cudaFuncAttributeMaxDynamicSharedMemorySize, SMEM_BYTES);

    dim3 grid(BB * (NN / QPB));   // 256 blocks
    dim3 block(THREADS);
    knn_edge_kernel<<<grid, block, SMEM_BYTES>>>(cloud, out);
}